// round 12
// baseline (speedup 1.0000x reference)
#include <cuda_runtime.h>
#include <stdint.h>

#define D_DIM   10000
#define T_STEPS 2048
#define TN      2046            /* ngram terms */
#define GROUPS  81              /* column groups, stride 124, window 128 */
#define SSPLIT  3               /* t-splits per group (2046 = 3*682) */
#define TCHUNK  682
#define WCH     43              /* ceil(682/16) steps per warp */
#define IDXN    684             /* staged idx entries per block */

__device__ float g_sample[D_DIM];
__device__ int   g_count[D_DIM];
__device__ float g_comb[D_DIM];

__constant__ int c_featIdx[29] = {
    546,547,548,550,553,555,556,557,558,559,560,561,562,564,
    565,566,569,575,579,580,581,582,583,584,587,592,597,598,599
};

/* ---------- kernel 1: comb precompute + zero accumulators/counters ---------- */
__global__ void __launch_bounds__(256) k_combine(const float* __restrict__ feat,
                                                 const float* __restrict__ feat_w,
                                                 const float* __restrict__ feat_b,
                                                 const float* __restrict__ mfcc_w,
                                                 const float* __restrict__ mfcc_b)
{
    __shared__ float s_feat[600];
    __shared__ float s_fh[8][32];
    const int tid = threadIdx.x;

    /* zero the ngram accumulators / completion counters for this block's 8 d's */
    const int zb = blockIdx.x * 8;
    if (tid < 8)            g_sample[zb + tid] = 0.0f;
    else if (tid < 16)      g_count[zb + tid - 8] = 0;

    for (int i = tid; i < 600; i += 256) s_feat[i] = feat[i];
    __syncthreads();

    const int warpId = tid >> 5;
    const int lane   = tid & 31;
    const int d      = blockIdx.x * 8 + warpId;
    if (d >= D_DIM) return;

    /* batched loads: ~26 LDGs in flight before any reduction */
    float w0[6], w1[6], w2[6], bias[6];
#pragma unroll
    for (int k = 0; k < 6; ++k) {
        const float* wrow = mfcc_w + (k * D_DIM + d) * 91;
        w0[k]   = wrow[lane];
        w1[k]   = wrow[32 + lane];
        w2[k]   = (lane < 27) ? wrow[64 + lane] : 0.0f;
        bias[k] = mfcc_b[k * D_DIM + d];
    }
    float fwv = 0.0f, fbv = 0.0f, sv = 0.0f;
    if (lane < 29) {
        fwv = feat_w[lane * D_DIM + d];
        fbv = feat_b[lane * D_DIM + d];
        sv  = s_feat[c_featIdx[lane]];
    }

    float prod = 1.0f;
#pragma unroll
    for (int k = 0; k < 6; ++k) {
        float a = w0[k] * s_feat[k * 91 + lane]
                + w1[k] * s_feat[k * 91 + 32 + lane]
                + w2[k] * s_feat[k * 91 + 64 + ((lane < 27) ? lane : 0)];
#pragma unroll
        for (int off = 16; off; off >>= 1) a += __shfl_xor_sync(0xffffffffu, a, off);
        prod *= cosf(a + bias[k]) * sinf(a);
    }

    float fh = 0.0f;
    if (lane < 29) {
        const float pw = sv * fwv;
        fh = cosf(pw + fbv) * sinf(pw);
    }
    s_fh[warpId][lane] = fh;
    __syncwarp();

    if (lane == 0) {
        const float* f = s_fh[warpId];
        g_comb[d] =
              f[0]  * f[8]  * f[13]
            + f[1]  * f[9]  * f[14]
            + f[2]  * f[10] * f[15]
            + f[3]  * f[4]
            + f[5]  * f[7]  * f[22] * f[6]  * f[23] * f[19] * f[18]
                    * f[20] * f[21] * f[26] * f[28] * f[27]
            + f[11] + f[12]
            + f[16] * f[24]
            + f[17] + f[25]
            + prod;
    }
}

/* ---------- kernel 2: ngram (1-plane sign table + per-lane key XOR) ---------- */
__global__ void __launch_bounds__(512) k_ngram(const float* __restrict__ signals,
                                               const float* __restrict__ keys,
                                               const float* __restrict__ lw,
                                               float* __restrict__ out)
{
    __shared__ uint32_t s_lw[3200];     /* lw sign plane: l*32 + wd, {0,1} bytes (1=pos) */
    __shared__ uint32_t s_keys[128];    /* key sign words: c*32 + wd */
    __shared__ int      s_acc[128];
    __shared__ uint4    s_idx[IDXN];

    const int tid  = threadIdx.x;
    const int g    = blockIdx.x / SSPLIT;
    const int s    = blockIdx.x % SSPLIT;
    const int col0 = g * 124;
    const int tb   = s * TCHUNK;

    /* key sign words + zero acc */
    if (tid < 128) {
        const int c = tid >> 5, wd = tid & 31;
        int col = col0 + 4 * wd;
        if (col >= D_DIM) col -= D_DIM;          /* only group 80 wraps; 4-aligned */
        const float4 kf = *(const float4*)(keys + c * D_DIM + col);
        s_keys[tid] = ((~__float_as_uint(kf.x)) >> 31)
                    | (((~__float_as_uint(kf.y)) >> 31) << 8)
                    | (((~__float_as_uint(kf.z)) >> 31) << 16)
                    | (((~__float_as_uint(kf.w)) >> 31) << 24);
        s_acc[tid] = 0;
    }

    /* level indices for this block's t-range */
    for (int i = tid; i < IDXN; i += 512) {
        const int t = tb + i;
        if (t < T_STEPS) {
            const float4 sg = *(const float4*)(signals + t * 4);
            float f0 = fminf(fmaxf(sg.x, 0.0f), 1.0f);
            float f1 = fminf(fmaxf(sg.y, 0.0f), 1.0f);
            float f2 = fminf(fmaxf(sg.z, 0.0f), 1.0f);
            float f3 = fminf(fmaxf(sg.w, 0.0f), 1.0f);
            int l0 = min(max((int)rintf(f0 * 99.0f), 0), 99);
            int l1 = min(max((int)rintf(f1 * 99.0f), 0), 99);
            int l2 = min(max((int)rintf(f2 * 99.0f), 0), 99);
            int l3 = min(max((int)rintf(f3 * 99.0f), 0), 99);
            s_idx[i] = make_uint4(l0 * 32, l1 * 32, l2 * 32, l3 * 32);
        }
    }

    /* lw sign plane: 100 rows x 32 words */
#pragma unroll 2
    for (int wl = tid; wl < 3200; wl += 512) {
        const int l = wl >> 5, wd = wl & 31;
        int col = col0 + 4 * wd;
        if (col >= D_DIM) col -= D_DIM;
        const float4 wf = *(const float4*)(lw + l * D_DIM + col);
        s_lw[wl] = ((~__float_as_uint(wf.x)) >> 31)
                 | (((~__float_as_uint(wf.y)) >> 31) << 8)
                 | (((~__float_as_uint(wf.z)) >> 31) << 16)
                 | (((~__float_as_uint(wf.w)) >> 31) << 24);
    }
    __syncthreads();

    const int warp = tid >> 5;
    const int lane = tid & 31;
    const int t0 = tb + warp * WCH;
    const int i1 = min(min(t0 + WCH, tb + TCHUNK), TN);

    /* per-lane channel keys, bias folded: byte = slw ^ skey ^ 1 */
    const uint32_t kinv0 = s_keys[lane]       ^ 0x01010101u;
    const uint32_t kinv1 = s_keys[32 + lane]  ^ 0x01010101u;
    const uint32_t kinv2 = s_keys[64 + lane]  ^ 0x01010101u;
    const uint32_t kinv3 = s_keys[96 + lane]  ^ 0x01010101u;

    if (t0 < i1) {
        int a2x, a2y, a2z, a2w;             /* s2 @ t-2 */
        int b2x, b2y, b2z, b2w;             /* s2 @ t-1 */
        int b1x, b1y, b1z, b1w;             /* s1 @ t-1 */
        int ax = 0, ay = 0, az = 0, aw = 0;

        /* per_t = 2s-4; carry v = s-2 (dp4a acc -2); x8 restored at writeback */
#define NG_STEP(LI, V0,V1,V2,V3, S1X,S1Y,S1Z,S1W, S2X,S2Y,S2Z,S2W)             \
        {                                                                       \
            const uint4 ix = s_idx[LI];                                         \
            const uint32_t u0 = s_lw[ix.x + lane] ^ kinv0;                      \
            const uint32_t u1 = s_lw[ix.y + lane] ^ kinv1;                      \
            const uint32_t u2 = s_lw[ix.z + lane] ^ kinv2;                      \
            const uint32_t u3 = s_lw[ix.w + lane] ^ kinv3;                      \
            const uint32_t sm4 = (u0 + u1) + (u2 + u3); /* byte sums <= 4 */    \
            const uint32_t pm4 = __shfl_up_sync(0xffffffffu, sm4, 1);           \
            V0 = __dp4a((int)sm4, 0x00000001, -2);                              \
            V1 = __dp4a((int)sm4, 0x00000100, -2);                              \
            V2 = __dp4a((int)sm4, 0x00010000, -2);                              \
            V3 = __dp4a((int)sm4, 0x01000000, -2);                              \
            const int n3 = __dp4a((int)pm4, 0x01000000, -2);                    \
            const int n2 = __dp4a((int)pm4, 0x00010000, -2);                    \
            S1X = n3; S1Y = V0; S1Z = V1; S1W = V2;                             \
            S2X = n2; S2Y = n3; S2Z = V0; S2W = V1;                             \
        }

        {   /* warm-up rows t0, t0+1 (local idx) */
            int v0,v1,v2,v3, d1x,d1y,d1z,d1w;
            NG_STEP(t0 - tb,     v0,v1,v2,v3, d1x,d1y,d1z,d1w, a2x,a2y,a2z,a2w);
            NG_STEP(t0 - tb + 1, v0,v1,v2,v3, b1x,b1y,b1z,b1w, b2x,b2y,b2z,b2w);
        }

#pragma unroll 4
        for (int li = t0 - tb + 2; li < i1 - tb + 2; ++li) {
            int v0,v1,v2,v3, c1x,c1y,c1z,c1w, c2x,c2y,c2z,c2w;
            NG_STEP(li, v0,v1,v2,v3, c1x,c1y,c1z,c1w, c2x,c2y,c2z,c2w);
            ax += a2x * b1x * v0;
            ay += a2y * b1y * v1;
            az += a2z * b1z * v2;
            aw += a2w * b1w * v3;
            a2x = b2x; a2y = b2y; a2z = b2z; a2w = b2w;
            b2x = c2x; b2y = c2y; b2z = c2z; b2w = c2w;
            b1x = c1x; b1y = c1y; b1z = c1z; b1w = c1w;
        }
#undef NG_STEP

        atomicAdd(&s_acc[4*lane + 0], ax);
        atomicAdd(&s_acc[4*lane + 1], ay);
        atomicAdd(&s_acc[4*lane + 2], az);
        atomicAdd(&s_acc[4*lane + 3], aw);
    }

    __syncthreads();
    /* window positions 2..125 -> global; 3rd finisher per column quantizes */
    if (tid >= 2 && tid < 126) {
        int o = col0 + tid;
        if (o <= D_DIM + 1) {                /* dedupe wrap overlap */
            if (o >= D_DIM) o -= D_DIM;
            atomicAdd(&g_sample[o], (float)(s_acc[tid] * 8));
            __threadfence();
            if (atomicAdd(&g_count[o], 1) == SSPLIT - 1) {
                const float sv = atomicAdd(&g_sample[o], 0.0f) * g_comb[o];
                out[o] = (sv > 0.0f) ? 1.0f : -1.0f;
            }
        }
    }
}

/* ---------- launcher ---------- */
extern "C" void kernel_launch(void* const* d_in, const int* in_sizes, int n_in,
                              void* d_out, int out_size)
{
    (void)in_sizes; (void)n_in; (void)out_size;
    const float* signals = (const float*)d_in[0];
    const float* feat    = (const float*)d_in[1];
    const float* keys    = (const float*)d_in[2];
    const float* lw      = (const float*)d_in[3];
    const float* fw      = (const float*)d_in[4];
    const float* fb      = (const float*)d_in[5];
    const float* mw      = (const float*)d_in[6];
    const float* mb      = (const float*)d_in[7];
    float* out = (float*)d_out;

    k_combine<<<1250, 256>>>(feat, fw, fb, mw, mb);
    k_ngram<<<GROUPS * SSPLIT, 512>>>(signals, keys, lw, out);
}

// round 14
// speedup vs baseline: 1.1225x; 1.1225x over previous
#include <cuda_runtime.h>
#include <stdint.h>

#define D_DIM   10000
#define T_STEPS 2048
#define TN      2046            /* ngram terms */
#define GROUPS  81              /* column groups, stride 124, window 128 */
#define SSPLIT  6               /* t-splits per group (2046 = 6*341) */
#define TCHUNK  341
#define WCH     22              /* ceil(341/16) steps per warp */
#define IDXN    344             /* staged idx entries per block */

__device__ float g_sample[D_DIM];
__device__ int   g_count[D_DIM];
__device__ float g_comb[D_DIM];

__constant__ int c_featIdx[29] = {
    546,547,548,550,553,555,556,557,558,559,560,561,562,564,
    565,566,569,575,579,580,581,582,583,584,587,592,597,598,599
};

/* ---------- kernel 1 (PDL primary): comb precompute + zero acc/counters ---------- */
__global__ void __launch_bounds__(256) k_combine(const float* __restrict__ feat,
                                                 const float* __restrict__ feat_w,
                                                 const float* __restrict__ feat_b,
                                                 const float* __restrict__ mfcc_w,
                                                 const float* __restrict__ mfcc_b)
{
#if __CUDA_ARCH__ >= 900
    cudaTriggerProgrammaticLaunchCompletion();   /* let k_ngram start immediately */
#endif
    __shared__ float s_feat[600];
    __shared__ float s_fh[8][32];
    const int tid = threadIdx.x;

    /* zero the ngram accumulators / completion counters for this block's 8 d's */
    const int zb = blockIdx.x * 8;
    if (tid < 8)            g_sample[zb + tid] = 0.0f;
    else if (tid < 16)      g_count[zb + tid - 8] = 0;

    for (int i = tid; i < 600; i += 256) s_feat[i] = feat[i];
    __syncthreads();

    const int warpId = tid >> 5;
    const int lane   = tid & 31;
    const int d      = blockIdx.x * 8 + warpId;
    if (d >= D_DIM) return;

    /* batched loads: ~26 LDGs in flight before any reduction */
    float w0[6], w1[6], w2[6], bias[6];
#pragma unroll
    for (int k = 0; k < 6; ++k) {
        const float* wrow = mfcc_w + (k * D_DIM + d) * 91;
        w0[k]   = wrow[lane];
        w1[k]   = wrow[32 + lane];
        w2[k]   = (lane < 27) ? wrow[64 + lane] : 0.0f;
        bias[k] = mfcc_b[k * D_DIM + d];
    }
    float fwv = 0.0f, fbv = 0.0f, sv = 0.0f;
    if (lane < 29) {
        fwv = feat_w[lane * D_DIM + d];
        fbv = feat_b[lane * D_DIM + d];
        sv  = s_feat[c_featIdx[lane]];
    }

    float prod = 1.0f;
#pragma unroll
    for (int k = 0; k < 6; ++k) {
        float a = w0[k] * s_feat[k * 91 + lane]
                + w1[k] * s_feat[k * 91 + 32 + lane]
                + w2[k] * s_feat[k * 91 + 64 + ((lane < 27) ? lane : 0)];
#pragma unroll
        for (int off = 16; off; off >>= 1) a += __shfl_xor_sync(0xffffffffu, a, off);
        prod *= cosf(a + bias[k]) * sinf(a);
    }

    float fh = 0.0f;
    if (lane < 29) {
        const float pw = sv * fwv;
        fh = cosf(pw + fbv) * sinf(pw);
    }
    s_fh[warpId][lane] = fh;
    __syncwarp();

    if (lane == 0) {
        const float* f = s_fh[warpId];
        g_comb[d] =
              f[0]  * f[8]  * f[13]
            + f[1]  * f[9]  * f[14]
            + f[2]  * f[10] * f[15]
            + f[3]  * f[4]
            + f[5]  * f[7]  * f[22] * f[6]  * f[23] * f[19] * f[18]
                    * f[20] * f[21] * f[26] * f[28] * f[27]
            + f[11] + f[12]
            + f[16] * f[24]
            + f[17] + f[25]
            + prod;
    }
}

/* ---------- kernel 2 (PDL secondary): ngram + fused quantize ---------- */
__global__ void __launch_bounds__(512, 3) k_ngram(const float* __restrict__ signals,
                                                  const float* __restrict__ keys,
                                                  const float* __restrict__ lw,
                                                  float* __restrict__ out)
{
    __shared__ uint32_t s_lw[3200];     /* lw sign plane: l*32 + wd, {0,1} bytes (1=pos) */
    __shared__ uint32_t s_keys[128];    /* key sign words: c*32 + wd */
    __shared__ int      s_acc[128];
    __shared__ uint4    s_idx[IDXN];    /* BYTE offsets l*128 per channel */

    const int tid  = threadIdx.x;
    const int g    = blockIdx.x / SSPLIT;
    const int s    = blockIdx.x % SSPLIT;
    const int col0 = g * 124;
    const int tb   = s * TCHUNK;

    /* key sign words + zero acc */
    if (tid < 128) {
        const int c = tid >> 5, wd = tid & 31;
        int col = col0 + 4 * wd;
        if (col >= D_DIM) col -= D_DIM;          /* only group 80 wraps; 4-aligned */
        const float4 kf = *(const float4*)(keys + c * D_DIM + col);
        s_keys[tid] = ((~__float_as_uint(kf.x)) >> 31)
                    | (((~__float_as_uint(kf.y)) >> 31) << 8)
                    | (((~__float_as_uint(kf.z)) >> 31) << 16)
                    | (((~__float_as_uint(kf.w)) >> 31) << 24);
        s_acc[tid] = 0;
    }

    /* level indices (byte offsets) for this block's t-range */
    for (int i = tid; i < IDXN; i += 512) {
        const int t = tb + i;
        if (t < T_STEPS) {
            const float4 sg = *(const float4*)(signals + t * 4);
            float f0 = fminf(fmaxf(sg.x, 0.0f), 1.0f);
            float f1 = fminf(fmaxf(sg.y, 0.0f), 1.0f);
            float f2 = fminf(fmaxf(sg.z, 0.0f), 1.0f);
            float f3 = fminf(fmaxf(sg.w, 0.0f), 1.0f);
            int l0 = min(max((int)rintf(f0 * 99.0f), 0), 99);
            int l1 = min(max((int)rintf(f1 * 99.0f), 0), 99);
            int l2 = min(max((int)rintf(f2 * 99.0f), 0), 99);
            int l3 = min(max((int)rintf(f3 * 99.0f), 0), 99);
            s_idx[i] = make_uint4(l0 * 128, l1 * 128, l2 * 128, l3 * 128);
        }
    }

    /* lw sign plane: 100 rows x 32 words */
#pragma unroll 2
    for (int wl = tid; wl < 3200; wl += 512) {
        const int l = wl >> 5, wd = wl & 31;
        int col = col0 + 4 * wd;
        if (col >= D_DIM) col -= D_DIM;
        const float4 wf = *(const float4*)(lw + l * D_DIM + col);
        s_lw[wl] = ((~__float_as_uint(wf.x)) >> 31)
                 | (((~__float_as_uint(wf.y)) >> 31) << 8)
                 | (((~__float_as_uint(wf.z)) >> 31) << 16)
                 | (((~__float_as_uint(wf.w)) >> 31) << 24);
    }
    __syncthreads();

    const int warp = tid >> 5;
    const int lane = tid & 31;
    const int t0 = tb + warp * WCH;
    const int i1 = min(min(t0 + WCH, tb + TCHUNK), TN);

    /* per-lane channel keys, bias folded: byte = slw ^ skey ^ 1 */
    const uint32_t kinv0 = s_keys[lane]       ^ 0x01010101u;
    const uint32_t kinv1 = s_keys[32 + lane]  ^ 0x01010101u;
    const uint32_t kinv2 = s_keys[64 + lane]  ^ 0x01010101u;
    const uint32_t kinv3 = s_keys[96 + lane]  ^ 0x01010101u;
    const char* lwB = (const char*)s_lw + lane * 4;

    if (t0 < i1) {
        int a2x, a2y, a2z, a2w;             /* s2 @ t-2 */
        int b2x, b2y, b2z, b2w;             /* s2 @ t-1 */
        int b1x, b1y, b1z, b1w;             /* s1 @ t-1 */
        int ax = 0, ay = 0, az = 0, aw = 0;

        /* per_t = 2s-4; carry v = s-2 (dp4a acc -2); x8 restored at writeback */
#define NG_STEP(LI, V0,V1,V2,V3, S1X,S1Y,S1Z,S1W, S2X,S2Y,S2Z,S2W)             \
        {                                                                       \
            const uint4 ix = s_idx[LI];                                         \
            const uint32_t u0 = *(const uint32_t*)(lwB + ix.x) ^ kinv0;         \
            const uint32_t u1 = *(const uint32_t*)(lwB + ix.y) ^ kinv1;         \
            const uint32_t u2 = *(const uint32_t*)(lwB + ix.z) ^ kinv2;         \
            const uint32_t u3 = *(const uint32_t*)(lwB + ix.w) ^ kinv3;         \
            const uint32_t sm4 = (u0 + u1) + (u2 + u3); /* byte sums <= 4 */    \
            const uint32_t pm4 = __shfl_up_sync(0xffffffffu, sm4, 1);           \
            V0 = __dp4a((int)sm4, 0x00000001, -2);                              \
            V1 = __dp4a((int)sm4, 0x00000100, -2);                              \
            V2 = __dp4a((int)sm4, 0x00010000, -2);                              \
            V3 = __dp4a((int)sm4, 0x01000000, -2);                              \
            const int n3 = __dp4a((int)pm4, 0x01000000, -2);                    \
            const int n2 = __dp4a((int)pm4, 0x00010000, -2);                    \
            S1X = n3; S1Y = V0; S1Z = V1; S1W = V2;                             \
            S2X = n2; S2Y = n3; S2Z = V0; S2W = V1;                             \
        }

        {   /* warm-up rows t0, t0+1 (local idx) */
            int v0,v1,v2,v3, d1x,d1y,d1z,d1w;
            NG_STEP(t0 - tb,     v0,v1,v2,v3, d1x,d1y,d1z,d1w, a2x,a2y,a2z,a2w);
            NG_STEP(t0 - tb + 1, v0,v1,v2,v3, b1x,b1y,b1z,b1w, b2x,b2y,b2z,b2w);
        }

#pragma unroll 3
        for (int li = t0 - tb + 2; li < i1 - tb + 2; ++li) {
            int v0,v1,v2,v3, c1x,c1y,c1z,c1w, c2x,c2y,c2z,c2w;
            NG_STEP(li, v0,v1,v2,v3, c1x,c1y,c1z,c1w, c2x,c2y,c2z,c2w);
            ax += a2x * b1x * v0;
            ay += a2y * b1y * v1;
            az += a2z * b1z * v2;
            aw += a2w * b1w * v3;
            a2x = b2x; a2y = b2y; a2z = b2z; a2w = b2w;
            b2x = c2x; b2y = c2y; b2z = c2z; b2w = c2w;
            b1x = c1x; b1y = c1y; b1z = c1z; b1w = c1w;
        }
#undef NG_STEP

        atomicAdd(&s_acc[4*lane + 0], ax);
        atomicAdd(&s_acc[4*lane + 1], ay);
        atomicAdd(&s_acc[4*lane + 2], az);
        atomicAdd(&s_acc[4*lane + 3], aw);
    }

    __syncthreads();

#if __CUDA_ARCH__ >= 900
    cudaGridDependencySynchronize();    /* g_sample/g_count zeroed + g_comb ready */
#endif

    /* window positions 2..125 -> global; 6th finisher per column quantizes */
    if (tid >= 2 && tid < 126) {
        int o = col0 + tid;
        if (o <= D_DIM + 1) {                /* dedupe wrap overlap */
            if (o >= D_DIM) o -= D_DIM;
            atomicAdd(&g_sample[o], (float)(s_acc[tid] * 8));
            __threadfence();
            if (atomicAdd(&g_count[o], 1) == SSPLIT - 1) {
                const float sv = atomicAdd(&g_sample[o], 0.0f) * g_comb[o];
                out[o] = (sv > 0.0f) ? 1.0f : -1.0f;
            }
        }
    }
}

/* ---------- launcher: PDL pair on one stream ---------- */
extern "C" void kernel_launch(void* const* d_in, const int* in_sizes, int n_in,
                              void* d_out, int out_size)
{
    (void)in_sizes; (void)n_in; (void)out_size;
    const float* signals = (const float*)d_in[0];
    const float* feat    = (const float*)d_in[1];
    const float* keys    = (const float*)d_in[2];
    const float* lw      = (const float*)d_in[3];
    const float* fw      = (const float*)d_in[4];
    const float* fb      = (const float*)d_in[5];
    const float* mw      = (const float*)d_in[6];
    const float* mb      = (const float*)d_in[7];
    float* out = (float*)d_out;

    k_combine<<<1250, 256>>>(feat, fw, fb, mw, mb);

    cudaLaunchConfig_t cfg = {};
    cfg.gridDim  = dim3(GROUPS * SSPLIT);
    cfg.blockDim = dim3(512);
    cfg.dynamicSmemBytes = 0;
    cfg.stream = 0;
    cudaLaunchAttribute attr[1];
    attr[0].id = cudaLaunchAttributeProgrammaticStreamSerialization;
    attr[0].val.programmaticStreamSerializationAllowed = 1;
    cfg.attrs = attr;
    cfg.numAttrs = 1;
    cudaLaunchKernelEx(&cfg, k_ngram, signals, keys, lw, out);
}

// round 15
// speedup vs baseline: 1.1239x; 1.0013x over previous
#include <cuda_runtime.h>
#include <stdint.h>

#define D_DIM   10000
#define T_STEPS 2048
#define TN      2046            /* ngram terms */
#define GROUPS  81              /* column groups, stride 124, window 128 */
#define SSPLIT  5               /* t-splits per group */
#define TCHUNK  410             /* ceil(2046/5) */
#define WCH     26              /* ceil(410/16) steps per warp */
#define IDXN    412             /* staged idx entries per block */

__device__ float g_sample[D_DIM];
__device__ int   g_count[D_DIM];
__device__ float g_comb[D_DIM];

__constant__ int c_featIdx[29] = {
    546,547,548,550,553,555,556,557,558,559,560,561,562,564,
    565,566,569,575,579,580,581,582,583,584,587,592,597,598,599
};

/* ---------- kernel 1 (PDL primary): comb precompute + zero acc/counters ---------- */
__global__ void __launch_bounds__(256) k_combine(const float* __restrict__ feat,
                                                 const float* __restrict__ feat_w,
                                                 const float* __restrict__ feat_b,
                                                 const float* __restrict__ mfcc_w,
                                                 const float* __restrict__ mfcc_b)
{
#if __CUDA_ARCH__ >= 900
    cudaTriggerProgrammaticLaunchCompletion();   /* let k_ngram start immediately */
#endif
    __shared__ float s_feat[600];
    __shared__ float s_fh[8][32];
    const int tid = threadIdx.x;

    /* zero the ngram accumulators / completion counters for this block's 8 d's */
    const int zb = blockIdx.x * 8;
    if (tid < 8)            g_sample[zb + tid] = 0.0f;
    else if (tid < 16)      g_count[zb + tid - 8] = 0;

    for (int i = tid; i < 600; i += 256) s_feat[i] = feat[i];
    __syncthreads();

    const int warpId = tid >> 5;
    const int lane   = tid & 31;
    const int d      = blockIdx.x * 8 + warpId;
    if (d >= D_DIM) return;

    /* batched loads: ~26 LDGs in flight before any reduction */
    float w0[6], w1[6], w2[6], bias[6];
#pragma unroll
    for (int k = 0; k < 6; ++k) {
        const float* wrow = mfcc_w + (k * D_DIM + d) * 91;
        w0[k]   = wrow[lane];
        w1[k]   = wrow[32 + lane];
        w2[k]   = (lane < 27) ? wrow[64 + lane] : 0.0f;
        bias[k] = mfcc_b[k * D_DIM + d];
    }
    float fwv = 0.0f, fbv = 0.0f, sv = 0.0f;
    if (lane < 29) {
        fwv = feat_w[lane * D_DIM + d];
        fbv = feat_b[lane * D_DIM + d];
        sv  = s_feat[c_featIdx[lane]];
    }

    float prod = 1.0f;
#pragma unroll
    for (int k = 0; k < 6; ++k) {
        float a = w0[k] * s_feat[k * 91 + lane]
                + w1[k] * s_feat[k * 91 + 32 + lane]
                + w2[k] * s_feat[k * 91 + 64 + ((lane < 27) ? lane : 0)];
#pragma unroll
        for (int off = 16; off; off >>= 1) a += __shfl_xor_sync(0xffffffffu, a, off);
        prod *= cosf(a + bias[k]) * sinf(a);
    }

    float fh = 0.0f;
    if (lane < 29) {
        const float pw = sv * fwv;
        fh = cosf(pw + fbv) * sinf(pw);
    }
    s_fh[warpId][lane] = fh;
    __syncwarp();

    if (lane == 0) {
        const float* f = s_fh[warpId];
        g_comb[d] =
              f[0]  * f[8]  * f[13]
            + f[1]  * f[9]  * f[14]
            + f[2]  * f[10] * f[15]
            + f[3]  * f[4]
            + f[5]  * f[7]  * f[22] * f[6]  * f[23] * f[19] * f[18]
                    * f[20] * f[21] * f[26] * f[28] * f[27]
            + f[11] + f[12]
            + f[16] * f[24]
            + f[17] + f[25]
            + prod;
    }
}

/* ---------- kernel 2 (PDL secondary): ngram + fused quantize ---------- */
__global__ void __launch_bounds__(512, 2) k_ngram(const float* __restrict__ signals,
                                                  const float* __restrict__ keys,
                                                  const float* __restrict__ lw,
                                                  float* __restrict__ out)
{
    __shared__ uint32_t s_lw[3200];     /* lw sign plane: l*32 + wd, {0,1} bytes (1=pos) */
    __shared__ uint32_t s_keys[128];    /* key sign words: c*32 + wd */
    __shared__ int      s_acc[128];
    __shared__ uint4    s_idx[IDXN];    /* word offsets l*32 per channel */

    const int tid  = threadIdx.x;
    const int g    = blockIdx.x / SSPLIT;
    const int s    = blockIdx.x % SSPLIT;
    const int col0 = g * 124;
    const int tb   = s * TCHUNK;

    /* key sign words + zero acc */
    if (tid < 128) {
        const int c = tid >> 5, wd = tid & 31;
        int col = col0 + 4 * wd;
        if (col >= D_DIM) col -= D_DIM;          /* only group 80 wraps; 4-aligned */
        const float4 kf = *(const float4*)(keys + c * D_DIM + col);
        s_keys[tid] = ((~__float_as_uint(kf.x)) >> 31)
                    | (((~__float_as_uint(kf.y)) >> 31) << 8)
                    | (((~__float_as_uint(kf.z)) >> 31) << 16)
                    | (((~__float_as_uint(kf.w)) >> 31) << 24);
        s_acc[tid] = 0;
    }

    /* level indices (word offsets) for this block's t-range */
    for (int i = tid; i < IDXN; i += 512) {
        const int t = tb + i;
        if (t < T_STEPS) {
            const float4 sg = *(const float4*)(signals + t * 4);
            float f0 = fminf(fmaxf(sg.x, 0.0f), 1.0f);
            float f1 = fminf(fmaxf(sg.y, 0.0f), 1.0f);
            float f2 = fminf(fmaxf(sg.z, 0.0f), 1.0f);
            float f3 = fminf(fmaxf(sg.w, 0.0f), 1.0f);
            int l0 = min(max((int)rintf(f0 * 99.0f), 0), 99);
            int l1 = min(max((int)rintf(f1 * 99.0f), 0), 99);
            int l2 = min(max((int)rintf(f2 * 99.0f), 0), 99);
            int l3 = min(max((int)rintf(f3 * 99.0f), 0), 99);
            s_idx[i] = make_uint4(l0 * 32, l1 * 32, l2 * 32, l3 * 32);
        }
    }

    /* lw sign plane: 100 rows x 32 words */
#pragma unroll 2
    for (int wl = tid; wl < 3200; wl += 512) {
        const int l = wl >> 5, wd = wl & 31;
        int col = col0 + 4 * wd;
        if (col >= D_DIM) col -= D_DIM;
        const float4 wf = *(const float4*)(lw + l * D_DIM + col);
        s_lw[wl] = ((~__float_as_uint(wf.x)) >> 31)
                 | (((~__float_as_uint(wf.y)) >> 31) << 8)
                 | (((~__float_as_uint(wf.z)) >> 31) << 16)
                 | (((~__float_as_uint(wf.w)) >> 31) << 24);
    }
    __syncthreads();

    const int warp = tid >> 5;
    const int lane = tid & 31;
    const int t0 = tb + warp * WCH;
    const int i1 = min(min(t0 + WCH, tb + TCHUNK), TN);

    /* per-lane channel keys, bias folded: byte = slw ^ skey ^ 1 */
    const uint32_t kinv0 = s_keys[lane]       ^ 0x01010101u;
    const uint32_t kinv1 = s_keys[32 + lane]  ^ 0x01010101u;
    const uint32_t kinv2 = s_keys[64 + lane]  ^ 0x01010101u;
    const uint32_t kinv3 = s_keys[96 + lane]  ^ 0x01010101u;

    if (t0 < i1) {
        int a2x, a2y, a2z, a2w;             /* s2 @ t-2 */
        int b2x, b2y, b2z, b2w;             /* s2 @ t-1 */
        int b1x, b1y, b1z, b1w;             /* s1 @ t-1 */
        int ax = 0, ay = 0, az = 0, aw = 0;

        /* per_t = 2s-4; carry v = s-2 (dp4a acc -2); x8 restored at writeback.
           n3/n2 come from prev lane's v3/v2 via 2 shfls (fma-pipe relief). */
#define NG_STEP(LI, V0,V1,V2,V3, S1X,S1Y,S1Z,S1W, S2X,S2Y,S2Z,S2W)             \
        {                                                                       \
            const uint4 ix = s_idx[LI];                                         \
            const uint32_t u0 = s_lw[ix.x + lane] ^ kinv0;                      \
            const uint32_t u1 = s_lw[ix.y + lane] ^ kinv1;                      \
            const uint32_t u2 = s_lw[ix.z + lane] ^ kinv2;                      \
            const uint32_t u3 = s_lw[ix.w + lane] ^ kinv3;                      \
            const uint32_t sm4 = (u0 + u1) + (u2 + u3); /* byte sums <= 4 */    \
            V0 = __dp4a((int)sm4, 0x00000001, -2);                              \
            V1 = __dp4a((int)sm4, 0x00000100, -2);                              \
            V2 = __dp4a((int)sm4, 0x00010000, -2);                              \
            V3 = __dp4a((int)sm4, 0x01000000, -2);                              \
            const int n3 = __shfl_up_sync(0xffffffffu, V3, 1);                  \
            const int n2 = __shfl_up_sync(0xffffffffu, V2, 1);                  \
            S1X = n3; S1Y = V0; S1Z = V1; S1W = V2;                             \
            S2X = n2; S2Y = n3; S2Z = V0; S2W = V1;                             \
        }

        {   /* warm-up rows t0, t0+1 (local idx) */
            int v0,v1,v2,v3, d1x,d1y,d1z,d1w;
            NG_STEP(t0 - tb,     v0,v1,v2,v3, d1x,d1y,d1z,d1w, a2x,a2y,a2z,a2w);
            NG_STEP(t0 - tb + 1, v0,v1,v2,v3, b1x,b1y,b1z,b1w, b2x,b2y,b2z,b2w);
        }

#pragma unroll 4
        for (int li = t0 - tb + 2; li < i1 - tb + 2; ++li) {
            int v0,v1,v2,v3, c1x,c1y,c1z,c1w, c2x,c2y,c2z,c2w;
            NG_STEP(li, v0,v1,v2,v3, c1x,c1y,c1z,c1w, c2x,c2y,c2z,c2w);
            ax += a2x * b1x * v0;
            ay += a2y * b1y * v1;
            az += a2z * b1z * v2;
            aw += a2w * b1w * v3;
            a2x = b2x; a2y = b2y; a2z = b2z; a2w = b2w;
            b2x = c2x; b2y = c2y; b2z = c2z; b2w = c2w;
            b1x = c1x; b1y = c1y; b1z = c1z; b1w = c1w;
        }
#undef NG_STEP

        atomicAdd(&s_acc[4*lane + 0], ax);
        atomicAdd(&s_acc[4*lane + 1], ay);
        atomicAdd(&s_acc[4*lane + 2], az);
        atomicAdd(&s_acc[4*lane + 3], aw);
    }

    __syncthreads();

#if __CUDA_ARCH__ >= 900
    cudaGridDependencySynchronize();    /* g_sample/g_count zeroed + g_comb ready */
#endif

    /* window positions 2..125 -> global; 5th finisher per column quantizes */
    if (tid >= 2 && tid < 126) {
        int o = col0 + tid;
        if (o <= D_DIM + 1) {                /* dedupe wrap overlap */
            if (o >= D_DIM) o -= D_DIM;
            atomicAdd(&g_sample[o], (float)(s_acc[tid] * 8));
            __threadfence();
            if (atomicAdd(&g_count[o], 1) == SSPLIT - 1) {
                const float sv = atomicAdd(&g_sample[o], 0.0f) * g_comb[o];
                out[o] = (sv > 0.0f) ? 1.0f : -1.0f;
            }
        }
    }
}

/* ---------- launcher: PDL pair on one stream ---------- */
extern "C" void kernel_launch(void* const* d_in, const int* in_sizes, int n_in,
                              void* d_out, int out_size)
{
    (void)in_sizes; (void)n_in; (void)out_size;
    const float* signals = (const float*)d_in[0];
    const float* feat    = (const float*)d_in[1];
    const float* keys    = (const float*)d_in[2];
    const float* lw      = (const float*)d_in[3];
    const float* fw      = (const float*)d_in[4];
    const float* fb      = (const float*)d_in[5];
    const float* mw      = (const float*)d_in[6];
    const float* mb      = (const float*)d_in[7];
    float* out = (float*)d_out;

    k_combine<<<1250, 256>>>(feat, fw, fb, mw, mb);

    cudaLaunchConfig_t cfg = {};
    cfg.gridDim  = dim3(GROUPS * SSPLIT);
    cfg.blockDim = dim3(512);
    cfg.dynamicSmemBytes = 0;
    cfg.stream = 0;
    cudaLaunchAttribute attr[1];
    attr[0].id = cudaLaunchAttributeProgrammaticStreamSerialization;
    attr[0].val.programmaticStreamSerializationAllowed = 1;
    cfg.attrs = attr;
    cfg.numAttrs = 1;
    cudaLaunchKernelEx(&cfg, k_ngram, signals, keys, lw, out);
}

// round 16
// speedup vs baseline: 1.1667x; 1.0381x over previous
#include <cuda_runtime.h>
#include <stdint.h>

#define D_DIM   10000
#define T_STEPS 2048
#define TN      2046            /* ngram terms */
#define GROUPS  81              /* column groups, stride 124, window 128 */
#define SSPLIT  7               /* t-splits per group */
#define TCHUNK  293             /* ceil(2046/7) */
#define NWARPS  8               /* 256-thread blocks */
#define WCH     37              /* ceil(293/8) steps per warp */
#define IDXN    296             /* staged idx entries per block */

__device__ float g_sample[D_DIM];
__device__ int   g_count[D_DIM];
__device__ float g_comb[D_DIM];

__constant__ int c_featIdx[29] = {
    546,547,548,550,553,555,556,557,558,559,560,561,562,564,
    565,566,569,575,579,580,581,582,583,584,587,592,597,598,599
};

/* ---------- kernel 1 (PDL primary): comb precompute + zero acc/counters ---------- */
__global__ void __launch_bounds__(256) k_combine(const float* __restrict__ feat,
                                                 const float* __restrict__ feat_w,
                                                 const float* __restrict__ feat_b,
                                                 const float* __restrict__ mfcc_w,
                                                 const float* __restrict__ mfcc_b)
{
#if __CUDA_ARCH__ >= 900
    cudaTriggerProgrammaticLaunchCompletion();   /* let k_ngram start immediately */
#endif
    __shared__ float s_feat[600];
    __shared__ float s_fh[8][32];
    const int tid = threadIdx.x;

    /* zero the ngram accumulators / completion counters for this block's 8 d's */
    const int zb = blockIdx.x * 8;
    if (tid < 8)            g_sample[zb + tid] = 0.0f;
    else if (tid < 16)      g_count[zb + tid - 8] = 0;

    for (int i = tid; i < 600; i += 256) s_feat[i] = feat[i];
    __syncthreads();

    const int warpId = tid >> 5;
    const int lane   = tid & 31;
    const int d      = blockIdx.x * 8 + warpId;
    if (d >= D_DIM) return;

    /* batched loads: ~26 LDGs in flight before any reduction */
    float w0[6], w1[6], w2[6], bias[6];
#pragma unroll
    for (int k = 0; k < 6; ++k) {
        const float* wrow = mfcc_w + (k * D_DIM + d) * 91;
        w0[k]   = wrow[lane];
        w1[k]   = wrow[32 + lane];
        w2[k]   = (lane < 27) ? wrow[64 + lane] : 0.0f;
        bias[k] = mfcc_b[k * D_DIM + d];
    }
    float fwv = 0.0f, fbv = 0.0f, sv = 0.0f;
    if (lane < 29) {
        fwv = feat_w[lane * D_DIM + d];
        fbv = feat_b[lane * D_DIM + d];
        sv  = s_feat[c_featIdx[lane]];
    }

    float prod = 1.0f;
#pragma unroll
    for (int k = 0; k < 6; ++k) {
        float a = w0[k] * s_feat[k * 91 + lane]
                + w1[k] * s_feat[k * 91 + 32 + lane]
                + w2[k] * s_feat[k * 91 + 64 + ((lane < 27) ? lane : 0)];
#pragma unroll
        for (int off = 16; off; off >>= 1) a += __shfl_xor_sync(0xffffffffu, a, off);
        prod *= cosf(a + bias[k]) * sinf(a);
    }

    float fh = 0.0f;
    if (lane < 29) {
        const float pw = sv * fwv;
        fh = cosf(pw + fbv) * sinf(pw);
    }
    s_fh[warpId][lane] = fh;
    __syncwarp();

    if (lane == 0) {
        const float* f = s_fh[warpId];
        g_comb[d] =
              f[0]  * f[8]  * f[13]
            + f[1]  * f[9]  * f[14]
            + f[2]  * f[10] * f[15]
            + f[3]  * f[4]
            + f[5]  * f[7]  * f[22] * f[6]  * f[23] * f[19] * f[18]
                    * f[20] * f[21] * f[26] * f[28] * f[27]
            + f[11] + f[12]
            + f[16] * f[24]
            + f[17] + f[25]
            + prod;
    }
}

/* ---------- kernel 2 (PDL secondary): ngram + fused quantize ---------- */
__global__ void __launch_bounds__(256, 4) k_ngram(const float* __restrict__ signals,
                                                  const float* __restrict__ keys,
                                                  const float* __restrict__ lw,
                                                  float* __restrict__ out)
{
    __shared__ uint32_t s_lw[3200];     /* lw sign plane: l*32 + wd, {0,1} bytes (1=pos) */
    __shared__ uint32_t s_keys[128];    /* key sign words: c*32 + wd */
    __shared__ int      s_acc[128];
    __shared__ uint4    s_idx[IDXN];    /* BYTE offsets l*128 per channel */

    const int tid  = threadIdx.x;
    const int g    = blockIdx.x / SSPLIT;
    const int s    = blockIdx.x % SSPLIT;
    const int col0 = g * 124;
    const int tb   = s * TCHUNK;

    /* key sign words + zero acc */
    if (tid < 128) {
        const int c = tid >> 5, wd = tid & 31;
        int col = col0 + 4 * wd;
        if (col >= D_DIM) col -= D_DIM;          /* only group 80 wraps; 4-aligned */
        const float4 kf = *(const float4*)(keys + c * D_DIM + col);
        s_keys[tid] = ((~__float_as_uint(kf.x)) >> 31)
                    | (((~__float_as_uint(kf.y)) >> 31) << 8)
                    | (((~__float_as_uint(kf.z)) >> 31) << 16)
                    | (((~__float_as_uint(kf.w)) >> 31) << 24);
        s_acc[tid] = 0;
    }

    /* level indices (byte offsets) for this block's t-range */
    for (int i = tid; i < IDXN; i += 256) {
        const int t = tb + i;
        if (t < T_STEPS) {
            const float4 sg = *(const float4*)(signals + t * 4);
            float f0 = fminf(fmaxf(sg.x, 0.0f), 1.0f);
            float f1 = fminf(fmaxf(sg.y, 0.0f), 1.0f);
            float f2 = fminf(fmaxf(sg.z, 0.0f), 1.0f);
            float f3 = fminf(fmaxf(sg.w, 0.0f), 1.0f);
            int l0 = min(max((int)rintf(f0 * 99.0f), 0), 99);
            int l1 = min(max((int)rintf(f1 * 99.0f), 0), 99);
            int l2 = min(max((int)rintf(f2 * 99.0f), 0), 99);
            int l3 = min(max((int)rintf(f3 * 99.0f), 0), 99);
            s_idx[i] = make_uint4(l0 * 128, l1 * 128, l2 * 128, l3 * 128);
        }
    }

    /* lw sign plane: 100 rows x 32 words */
#pragma unroll 4
    for (int wl = tid; wl < 3200; wl += 256) {
        const int l = wl >> 5, wd = wl & 31;
        int col = col0 + 4 * wd;
        if (col >= D_DIM) col -= D_DIM;
        const float4 wf = *(const float4*)(lw + l * D_DIM + col);
        s_lw[wl] = ((~__float_as_uint(wf.x)) >> 31)
                 | (((~__float_as_uint(wf.y)) >> 31) << 8)
                 | (((~__float_as_uint(wf.z)) >> 31) << 16)
                 | (((~__float_as_uint(wf.w)) >> 31) << 24);
    }
    __syncthreads();

    const int warp = tid >> 5;
    const int lane = tid & 31;
    const int t0 = tb + warp * WCH;
    const int i1 = min(min(t0 + WCH, tb + TCHUNK), TN);

    /* per-lane channel keys, bias folded: byte = slw ^ skey ^ 1 */
    const uint32_t kinv0 = s_keys[lane]       ^ 0x01010101u;
    const uint32_t kinv1 = s_keys[32 + lane]  ^ 0x01010101u;
    const uint32_t kinv2 = s_keys[64 + lane]  ^ 0x01010101u;
    const uint32_t kinv3 = s_keys[96 + lane]  ^ 0x01010101u;
    const char* lwB = (const char*)s_lw + lane * 4;

    if (t0 < i1) {
        int a2x, a2y, a2z, a2w;             /* s2 @ t-2 */
        int b2x, b2y, b2z, b2w;             /* s2 @ t-1 */
        int b1x, b1y, b1z, b1w;             /* s1 @ t-1 */
        int ax = 0, ay = 0, az = 0, aw = 0;

        /* per_t = 2s-4; carry v = s-2 (dp4a acc -2); x8 restored at writeback */
#define NG_STEP(LI, V0,V1,V2,V3, S1X,S1Y,S1Z,S1W, S2X,S2Y,S2Z,S2W)             \
        {                                                                       \
            const uint4 ix = s_idx[LI];                                         \
            const uint32_t u0 = *(const uint32_t*)(lwB + ix.x) ^ kinv0;         \
            const uint32_t u1 = *(const uint32_t*)(lwB + ix.y) ^ kinv1;         \
            const uint32_t u2 = *(const uint32_t*)(lwB + ix.z) ^ kinv2;         \
            const uint32_t u3 = *(const uint32_t*)(lwB + ix.w) ^ kinv3;         \
            const uint32_t sm4 = (u0 + u1) + (u2 + u3); /* byte sums <= 4 */    \
            V0 = __dp4a((int)sm4, 0x00000001, -2);                              \
            V1 = __dp4a((int)sm4, 0x00000100, -2);                              \
            V2 = __dp4a((int)sm4, 0x00010000, -2);                              \
            V3 = __dp4a((int)sm4, 0x01000000, -2);                              \
            const int n3 = __shfl_up_sync(0xffffffffu, V3, 1);                  \
            const int n2 = __shfl_up_sync(0xffffffffu, V2, 1);                  \
            S1X = n3; S1Y = V0; S1Z = V1; S1W = V2;                             \
            S2X = n2; S2Y = n3; S2Z = V0; S2W = V1;                             \
        }

        {   /* warm-up rows t0, t0+1 (local idx) */
            int v0,v1,v2,v3, d1x,d1y,d1z,d1w;
            NG_STEP(t0 - tb,     v0,v1,v2,v3, d1x,d1y,d1z,d1w, a2x,a2y,a2z,a2w);
            NG_STEP(t0 - tb + 1, v0,v1,v2,v3, b1x,b1y,b1z,b1w, b2x,b2y,b2z,b2w);
        }

#pragma unroll 6
        for (int li = t0 - tb + 2; li < i1 - tb + 2; ++li) {
            int v0,v1,v2,v3, c1x,c1y,c1z,c1w, c2x,c2y,c2z,c2w;
            NG_STEP(li, v0,v1,v2,v3, c1x,c1y,c1z,c1w, c2x,c2y,c2z,c2w);
            ax += a2x * b1x * v0;
            ay += a2y * b1y * v1;
            az += a2z * b1z * v2;
            aw += a2w * b1w * v3;
            a2x = b2x; a2y = b2y; a2z = b2z; a2w = b2w;
            b2x = c2x; b2y = c2y; b2z = c2z; b2w = c2w;
            b1x = c1x; b1y = c1y; b1z = c1z; b1w = c1w;
        }
#undef NG_STEP

        atomicAdd(&s_acc[4*lane + 0], ax);
        atomicAdd(&s_acc[4*lane + 1], ay);
        atomicAdd(&s_acc[4*lane + 2], az);
        atomicAdd(&s_acc[4*lane + 3], aw);
    }

    __syncthreads();

#if __CUDA_ARCH__ >= 900
    cudaGridDependencySynchronize();    /* g_sample/g_count zeroed + g_comb ready */
#endif

    /* window positions 2..125 -> global; 7th finisher per column quantizes */
    if (tid >= 2 && tid < 126) {
        int o = col0 + tid;
        if (o <= D_DIM + 1) {                /* dedupe wrap overlap */
            if (o >= D_DIM) o -= D_DIM;
            atomicAdd(&g_sample[o], (float)(s_acc[tid] * 8));
            __threadfence();
            if (atomicAdd(&g_count[o], 1) == SSPLIT - 1) {
                const float sv = atomicAdd(&g_sample[o], 0.0f) * g_comb[o];
                out[o] = (sv > 0.0f) ? 1.0f : -1.0f;
            }
        }
    }
}

/* ---------- launcher: PDL pair on one stream ---------- */
extern "C" void kernel_launch(void* const* d_in, const int* in_sizes, int n_in,
                              void* d_out, int out_size)
{
    (void)in_sizes; (void)n_in; (void)out_size;
    const float* signals = (const float*)d_in[0];
    const float* feat    = (const float*)d_in[1];
    const float* keys    = (const float*)d_in[2];
    const float* lw      = (const float*)d_in[3];
    const float* fw      = (const float*)d_in[4];
    const float* fb      = (const float*)d_in[5];
    const float* mw      = (const float*)d_in[6];
    const float* mb      = (const float*)d_in[7];
    float* out = (float*)d_out;

    k_combine<<<1250, 256>>>(feat, fw, fb, mw, mb);

    cudaLaunchConfig_t cfg = {};
    cfg.gridDim  = dim3(GROUPS * SSPLIT);
    cfg.blockDim = dim3(256);
    cfg.dynamicSmemBytes = 0;
    cfg.stream = 0;
    cudaLaunchAttribute attr[1];
    attr[0].id = cudaLaunchAttributeProgrammaticStreamSerialization;
    attr[0].val.programmaticStreamSerializationAllowed = 1;
    cfg.attrs = attr;
    cfg.numAttrs = 1;
    cudaLaunchKernelEx(&cfg, k_ngram, signals, keys, lw, out);
}